// round 1
// baseline (speedup 1.0000x reference)
#include <cuda_runtime.h>

// MultiModeVMD: 4 separable Gaussian blurs of x (sizes 17/13/9/5) + mode
// differences, fully fused. One read of x, one write per output element.
//
// out[m*B + b, c, h, w]:
//   mode0 = G17(x); mode1 = G13-G17; mode2 = G9-G13; mode3 = G5-G9; mode4 = x-G5

#define H_IMG 256
#define W_IMG 256
#define TW 64
#define TH 32
#define HALO 8
#define INW (TW + 2*HALO)   // 80
#define INH (TH + 2*HALO)   // 48
#define NT 256

// Normalized 1-D Gaussian weights (fp64-accurate, rounded to fp32).
// Returned from constant-indexed local arrays so fully-unrolled loops fold
// them into FFMA immediates (imm-form FFMA = 2x issue rate vs 3-reg FFMA).
__device__ __forceinline__ float wget(int f, int i) {
    const float W17[17] = {
        0.00095423f, 0.00316814f, 0.00896337f, 0.02160978f, 0.04439586f,
        0.07772262f, 0.11594853f, 0.14739947f, 0.15967594f, 0.14739947f,
        0.11594853f, 0.07772262f, 0.04439586f, 0.02160978f, 0.00896337f,
        0.00316814f, 0.00095423f};
    const float W13[13] = {
        0.00085704f, 0.00467984f, 0.01876795f, 0.05527917f, 0.11958186f,
        0.18998860f, 0.22169112f, 0.18998860f, 0.11958186f, 0.05527917f,
        0.01876795f, 0.00467984f, 0.00085704f};
    const float W9[9] = {
        0.00128539f, 0.01460861f, 0.08290719f, 0.23495371f, 0.33249028f,
        0.23495371f, 0.08290719f, 0.01460861f, 0.00128539f};
    const float W5[5] = {
        0.00256626f, 0.16552456f, 0.66381833f, 0.16552456f, 0.00256626f};
    if (f == 0) return W17[i];
    if (f == 1) return W13[i];
    if (f == 2) return W9[i];
    return W5[i];
}

// One separable blur of the shared input tile.
// H pass: each active thread computes 16 consecutive hblur outputs of one row
//   from a 32-float register window (2 LDS.128-amortized loads per output).
// V pass: each thread computes 8 consecutive rows of one column from an
//   (8+2R)-float register window (~ (8+2R)/8 LDS per output).
template<int R, int F>
__device__ __forceinline__ void filter_step(
    float (*sIn)[INW], float (*sHb)[TW], int tid, float (&cur)[8])
{
    constexpr int NTASKS = (TH + 2 * R) * 4;   // rows * 4 segments of 16 cols
    if (tid < NTASKS) {
        const int row  = (HALO - R) + (tid >> 2);
        const int segc = (tid & 3) << 4;
        float win[32];
#pragma unroll
        for (int k = 0; k < 32; k += 4) {
            float4 v4 = *reinterpret_cast<const float4*>(&sIn[row][segc + k]);
            win[k] = v4.x; win[k + 1] = v4.y; win[k + 2] = v4.z; win[k + 3] = v4.w;
        }
        float o[16];
#pragma unroll
        for (int m = 0; m < 16; ++m) {
            float acc = win[m + 8 - R] * wget(F, 0);
#pragma unroll
            for (int i = 1; i <= 2 * R; ++i)
                acc = fmaf(win[m + 8 - R + i], wget(F, i), acc);
            o[m] = acc;
        }
#pragma unroll
        for (int m = 0; m < 16; m += 4)
            *reinterpret_cast<float4*>(&sHb[row][segc + m]) =
                make_float4(o[m], o[m + 1], o[m + 2], o[m + 3]);
    }
    __syncthreads();   // hblur plane ready

    const int col = tid & (TW - 1);
    const int r0  = (tid >> 6) << 3;
    float v[8 + 2 * R];
#pragma unroll
    for (int k = 0; k < 8 + 2 * R; ++k)
        v[k] = sHb[r0 + HALO - R + k][col];
#pragma unroll
    for (int j = 0; j < 8; ++j) {
        float acc = v[j] * wget(F, 0);
#pragma unroll
        for (int i = 1; i <= 2 * R; ++i)
            acc = fmaf(v[j + i], wget(F, i), acc);
        cur[j] = acc;
    }
    __syncthreads();   // sHb consumed; safe for next filter to overwrite
}

__global__ void __launch_bounds__(NT)
vmd_kernel(const float* __restrict__ x, float* __restrict__ out, int planes)
{
    __shared__ __align__(16) float sIn[INH][INW];   // 15360 B
    __shared__ __align__(16) float sHb[INH][TW];    // 12288 B

    const int tid = threadIdx.x;
    const int p   = blockIdx.z;
    const int x0  = blockIdx.x * TW;
    const int y0  = blockIdx.y * TH;

    const float* __restrict__ xp = x + (size_t)p * (H_IMG * W_IMG);

    // Load 80x48 input tile with zero padding. 3840 elems / 256 thr = 15 iters.
#pragma unroll
    for (int i = 0; i < (INH * INW) / NT; ++i) {
        int idx = tid + i * NT;
        int r = idx / INW;
        int c = idx - r * INW;
        int gy = y0 - HALO + r;
        int gx = x0 - HALO + c;
        float v = 0.0f;
        if ((unsigned)gy < H_IMG && (unsigned)gx < W_IMG)
            v = __ldg(&xp[gy * W_IMG + gx]);
        sIn[r][c] = v;
    }
    __syncthreads();

    const int col = tid & (TW - 1);
    const int r0  = (tid >> 6) << 3;

    const size_t MODE = (size_t)planes * (H_IMG * W_IMG);
    float* op = out + (size_t)p * (H_IMG * W_IMG)
                    + (size_t)(y0 + r0) * W_IMG + (x0 + col);

    float prev[8], cur[8];

    filter_step<8, 0>(sIn, sHb, tid, cur);
#pragma unroll
    for (int j = 0; j < 8; ++j) {
        op[(size_t)j * W_IMG] = cur[j];
        prev[j] = cur[j];
    }

    filter_step<6, 1>(sIn, sHb, tid, cur);
#pragma unroll
    for (int j = 0; j < 8; ++j) {
        op[MODE + (size_t)j * W_IMG] = cur[j] - prev[j];
        prev[j] = cur[j];
    }

    filter_step<4, 2>(sIn, sHb, tid, cur);
#pragma unroll
    for (int j = 0; j < 8; ++j) {
        op[2 * MODE + (size_t)j * W_IMG] = cur[j] - prev[j];
        prev[j] = cur[j];
    }

    filter_step<2, 3>(sIn, sHb, tid, cur);
#pragma unroll
    for (int j = 0; j < 8; ++j) {
        op[3 * MODE + (size_t)j * W_IMG] = cur[j] - prev[j];
        op[4 * MODE + (size_t)j * W_IMG] =
            sIn[HALO + r0 + j][HALO + col] - cur[j];
    }
}

extern "C" void kernel_launch(void* const* d_in, const int* in_sizes, int n_in,
                              void* d_out, int out_size)
{
    const float* x = (const float*)d_in[0];
    float* out = (float*)d_out;
    const int planes = in_sizes[0] / (H_IMG * W_IMG);   // B*C = 512
    dim3 grid(W_IMG / TW, H_IMG / TH, planes);          // (4, 8, 512)
    vmd_kernel<<<grid, NT>>>(x, out, planes);
}

// round 2
// speedup vs baseline: 1.6601x; 1.6601x over previous
#include <cuda_runtime.h>

// MultiModeVMD: 4 separable Gaussian blurs (17/13/9/5 taps) of x + mode diffs,
// fully fused, one kernel. Conflict-free smem layout, paired H-passes.
//
// out[m*B + b, c, h, w]:
//   mode0=G17(x); mode1=G13-G17; mode2=G9-G13; mode3=G5-G9; mode4=x-G5

#define H_IMG 256
#define W_IMG 256
#define TW 64
#define TH 32
#define HALO 8
#define INW 80          // sIn stride (floats)
#define INH 48
#define HBW 68          // hblur plane stride: 68 % 32 = 4 -> bank-staggered rows
#define NT 256

// Normalized 1-D Gaussian weights. Compile-time indexed so every tap folds to
// an FFMA with immediate multiplier (rt=1 vs rt=2 for 3-reg FFMA).
__device__ __forceinline__ float wget(int f, int i) {
    const float W17[17] = {
        0.00095423f, 0.00316814f, 0.00896337f, 0.02160978f, 0.04439586f,
        0.07772262f, 0.11594853f, 0.14739947f, 0.15967594f, 0.14739947f,
        0.11594853f, 0.07772262f, 0.04439586f, 0.02160978f, 0.00896337f,
        0.00316814f, 0.00095423f};
    const float W13[13] = {
        0.00085704f, 0.00467984f, 0.01876795f, 0.05527917f, 0.11958186f,
        0.18998860f, 0.22169112f, 0.18998860f, 0.11958186f, 0.05527917f,
        0.01876795f, 0.00467984f, 0.00085704f};
    const float W9[9] = {
        0.00128539f, 0.01460861f, 0.08290719f, 0.23495371f, 0.33249028f,
        0.23495371f, 0.08290719f, 0.01460861f, 0.00128539f};
    const float W5[5] = {
        0.00256626f, 0.16552456f, 0.66381833f, 0.16552456f, 0.00256626f};
    if (f == 0) return W17[i];
    if (f == 1) return W13[i];
    if (f == 2) return W9[i];
    return W5[i];
}

// Paired horizontal pass: one register window feeds TWO filters' H-blurs.
// Warp layout: 2 rows per warp; lanes 0-15 -> row A, 16-31 -> row B;
// each lane computes 4 consecutive output columns. Every LDS.128 phase
// covers 32 consecutive floats -> conflict-free. STS.128 to stride-68
// planes likewise conflict-free.
template<int RMAX, int FA, int RA, int FB, int RB>
__device__ __forceinline__ void hpass_pair(
    const float (*sIn)[INW], float (*sA)[HBW], float (*sB)[HBW], int tid)
{
    constexpr int NROWS  = TH + 2 * RMAX;      // 48 or 40 (even)
    constexpr int NWR    = NROWS / 2;          // warp-rows
    constexpr int NITER  = (NWR + 7) / 8;      // 8 warps per CTA
    constexpr int LSTART = (8 - RMAX) & ~3;    // aligned window start offset
    constexpr int NW     = 4 + 2 * RMAX + ((8 - RMAX) - LSTART);
    constexpr int NLD    = (NW + 3) / 4;       // float4 loads per lane

    const int warp = tid >> 5;
    const int lane = tid & 31;
    const int rip  = lane >> 4;     // row in pair
    const int cg   = lane & 15;     // column group (4 cols)

#pragma unroll
    for (int it = 0; it < NITER; ++it) {
        const int wr = warp + it * 8;
        if ((NWR % 8 == 0) || (wr < NWR)) {
            const int row = (HALO - RMAX) + wr * 2 + rip;
            float win[NLD * 4];
#pragma unroll
            for (int k = 0; k < NLD; ++k) {
                float4 v = *reinterpret_cast<const float4*>(
                    &sIn[row][cg * 4 + LSTART + k * 4]);
                win[4 * k + 0] = v.x; win[4 * k + 1] = v.y;
                win[4 * k + 2] = v.z; win[4 * k + 3] = v.w;
            }
            float oa[4], ob[4];
#pragma unroll
            for (int m = 0; m < 4; ++m) {
                constexpr int BA = 8 - RA - LSTART;
                float acc = win[m + BA] * wget(FA, 0);
#pragma unroll
                for (int i = 1; i <= 2 * RA; ++i)
                    acc = fmaf(win[m + BA + i], wget(FA, i), acc);
                oa[m] = acc;
                constexpr int BB = 8 - RB - LSTART;
                float acb = win[m + BB] * wget(FB, 0);
#pragma unroll
                for (int i = 1; i <= 2 * RB; ++i)
                    acb = fmaf(win[m + BB + i], wget(FB, i), acb);
                ob[m] = acb;
            }
            *reinterpret_cast<float4*>(&sA[row][cg * 4]) =
                make_float4(oa[0], oa[1], oa[2], oa[3]);
            *reinterpret_cast<float4*>(&sB[row][cg * 4]) =
                make_float4(ob[0], ob[1], ob[2], ob[3]);
        }
    }
}

// Vertical pass: thread owns one column x 8 rows; sliding register window.
// Warp lanes cover 32 consecutive columns -> each scalar LDS = 1 wavefront.
template<int R, int F>
__device__ __forceinline__ void vpass(
    const float (*sP)[HBW], int col, int r0, float (&cur)[8])
{
    float v[8 + 2 * R];
#pragma unroll
    for (int k = 0; k < 8 + 2 * R; ++k)
        v[k] = sP[r0 + HALO - R + k][col];
#pragma unroll
    for (int j = 0; j < 8; ++j) {
        float acc = v[j] * wget(F, 0);
#pragma unroll
        for (int i = 1; i <= 2 * R; ++i)
            acc = fmaf(v[j + i], wget(F, i), acc);
        cur[j] = acc;
    }
}

__global__ void __launch_bounds__(NT)
vmd_kernel(const float* __restrict__ x, float* __restrict__ out, int planes)
{
    __shared__ __align__(16) float sIn[INH][INW];   // 15360 B
    __shared__ __align__(16) float sA[INH][HBW];    // 13056 B
    __shared__ __align__(16) float sB[INH][HBW];    // 13056 B  (41.5 KB total)

    const int tid = threadIdx.x;
    const int p   = blockIdx.z;
    const int x0  = blockIdx.x * TW;
    const int y0  = blockIdx.y * TH;

    const float* __restrict__ xp = x + (size_t)p * (H_IMG * W_IMG);

    // Load 80x48 input tile with zero padding (3840 elems, 15 iters).
#pragma unroll
    for (int i = 0; i < (INH * INW) / NT; ++i) {
        int idx = tid + i * NT;
        int r = idx / INW;
        int c = idx - r * INW;
        int gy = y0 - HALO + r;
        int gx = x0 - HALO + c;
        float v = 0.0f;
        if ((unsigned)gy < H_IMG && (unsigned)gx < W_IMG)
            v = xp[gy * W_IMG + gx];
        sIn[r][c] = v;
    }
    __syncthreads();

    const int col = tid & (TW - 1);
    const int r0  = (tid >> 6) << 3;

    const size_t MODE = (size_t)planes * (H_IMG * W_IMG);
    float* op = out + (size_t)p * (H_IMG * W_IMG)
                    + (size_t)(y0 + r0) * W_IMG + (x0 + col);

    float c0[8], c1[8], c2[8], c3[8];

    // ---- pair 1: G17 (R=8) + G13 (R=6) ----
    hpass_pair<8, 0, 8, 1, 6>(sIn, sA, sB, tid);
    __syncthreads();
    vpass<8, 0>(sA, col, r0, c0);
    vpass<6, 1>(sB, col, r0, c1);
#pragma unroll
    for (int j = 0; j < 8; ++j) {
        op[(size_t)j * W_IMG]        = c0[j];           // mode0 = G17
        op[MODE + (size_t)j * W_IMG] = c1[j] - c0[j];   // mode1 = G13-G17
    }
    __syncthreads();   // V reads of sA/sB complete before overwrite

    // ---- pair 2: G9 (R=4) + G5 (R=2) ----
    hpass_pair<4, 2, 4, 3, 2>(sIn, sA, sB, tid);
    __syncthreads();
    vpass<4, 2>(sA, col, r0, c2);
#pragma unroll
    for (int j = 0; j < 8; ++j)
        op[2 * MODE + (size_t)j * W_IMG] = c2[j] - c1[j];   // mode2 = G9-G13
    vpass<2, 3>(sB, col, r0, c3);
#pragma unroll
    for (int j = 0; j < 8; ++j) {
        op[3 * MODE + (size_t)j * W_IMG] = c3[j] - c2[j];   // mode3 = G5-G9
        op[4 * MODE + (size_t)j * W_IMG] =
            sIn[HALO + r0 + j][HALO + col] - c3[j];         // mode4 = x-G5
    }
}

extern "C" void kernel_launch(void* const* d_in, const int* in_sizes, int n_in,
                              void* d_out, int out_size)
{
    const float* x = (const float*)d_in[0];
    float* out = (float*)d_out;
    const int planes = in_sizes[0] / (H_IMG * W_IMG);   // B*C = 512
    dim3 grid(W_IMG / TW, H_IMG / TH, planes);          // (4, 8, 512)
    vmd_kernel<<<grid, NT>>>(x, out, planes);
}